// round 1
// baseline (speedup 1.0000x reference)
#include <cuda_runtime.h>
#include <math.h>

#define BB 64
#define TOK 64
#define NTK 456
#define LL 457
#define DD 256
#define HH 8
#define HD 32
#define NLAYER 4
#define FFD 1024
#define PHD 32
#define MM (BB*LL)   // 29248, divisible by 64

// ---------------- device scratch (static, allocation-guard-safe) ----------------
__device__ float g_x   [(size_t)MM*DD];            //  30 MB activations
__device__ float g_tmp [(size_t)MM*DD];            //  30 MB attn/ffn out
__device__ float g_qkv [(size_t)MM*3*DD];          //  90 MB
__device__ float g_sc  [512ull*457*457];           // 428 MB scores
__device__ float g_ffh [(size_t)MM*FFD];           // 120 MB ffn hidden
__device__ float g_hsc [MM];                       // head scores

// ---------------- input projection + CLS ----------------
__global__ __launch_bounds__(256) void k_input(
    const float* __restrict__ gene, const float* __restrict__ coords,
    const float* __restrict__ w_in, const float* __restrict__ b_in,
    const float* __restrict__ w_cls, const float* __restrict__ b_cls)
{
    int row = blockIdx.x;
    int b = row / LL, l = row % LL;
    int d = threadIdx.x;
    if (l == 0) {
        float acc = b_cls[d];
        #pragma unroll
        for (int k = 0; k < 3; k++) acc += coords[b*3 + k] * w_cls[k*DD + d];
        g_x[(size_t)row*DD + d] = acc;
    } else {
        __shared__ float sg[TOK];
        if (d < TOK) sg[d] = gene[(size_t)b*(NTK*TOK) + (size_t)(l-1)*TOK + d];
        __syncthreads();
        float acc = b_in[d];
        #pragma unroll 8
        for (int k = 0; k < TOK; k++) acc += sg[k] * w_in[k*DD + d];
        g_x[(size_t)row*DD + d] = acc;
    }
}

// ---------------- generic tiled SGEMM: C[M,N] = A[M,K] @ W[K,N] + bias, opt relu ----------------
// sel: 0: A=g_x  C=g_qkv   1: A=g_x  C=g_ffh   2: A=g_ffh  C=g_tmp
__global__ __launch_bounds__(256) void k_gemm(
    int sel, const float* __restrict__ W, const float* __restrict__ bias,
    int N, int K, int relu)
{
    const float* A; float* C;
    if (sel == 0)      { A = g_x;   C = g_qkv; }
    else if (sel == 1) { A = g_x;   C = g_ffh; }
    else               { A = g_ffh; C = g_tmp; }

    __shared__ float As[64][16];
    __shared__ float Bs[16][64];
    int tid = threadIdx.x;
    int tr = tid >> 4, tc = tid & 15;
    int bm = blockIdx.y * 64, bn = blockIdx.x * 64;
    float acc[4][4] = {};
    const float* Ab = A + (size_t)bm * K;

    for (int k0 = 0; k0 < K; k0 += 16) {
        #pragma unroll
        for (int e = 0; e < 4; e++) {
            int idx = tid + e*256;
            int r = idx >> 4, c = idx & 15;
            As[r][c] = Ab[(size_t)r*K + k0 + c];
        }
        #pragma unroll
        for (int e = 0; e < 4; e++) {
            int idx = tid + e*256;
            int kk = idx >> 6, n = idx & 63;
            Bs[kk][n] = W[(size_t)(k0+kk)*N + bn + n];
        }
        __syncthreads();
        #pragma unroll
        for (int kk = 0; kk < 16; kk++) {
            float a[4];
            #pragma unroll
            for (int i = 0; i < 4; i++) a[i] = As[tr*4 + i][kk];
            float4 bv = *reinterpret_cast<const float4*>(&Bs[kk][tc*4]);
            float bb[4] = {bv.x, bv.y, bv.z, bv.w};
            #pragma unroll
            for (int i = 0; i < 4; i++)
                #pragma unroll
                for (int j = 0; j < 4; j++)
                    acc[i][j] += a[i] * bb[j];
        }
        __syncthreads();
    }
    #pragma unroll
    for (int i = 0; i < 4; i++) {
        int r = bm + tr*4 + i;
        #pragma unroll
        for (int j = 0; j < 4; j++) {
            int c = bn + tc*4 + j;
            float v = acc[i][j] + bias[c];
            if (relu) v = fmaxf(v, 0.f);
            C[(size_t)r*N + c] = v;
        }
    }
}

// ---------------- scores = scale * Q@K^T + alibi ----------------
__global__ __launch_bounds__(256) void k_qk()
{
    int g = blockIdx.z;              // b*H + h
    int b = g >> 3, h = g & 7;
    int qi0 = blockIdx.y * 32, kj0 = blockIdx.x * 32;
    __shared__ float Qs[32][33], Ks[32][33];
    int tid = threadIdx.x;
    const float* qbase = g_qkv + (size_t)b*LL*768 + h*HD;
    const float* kbase = qbase + DD;
    #pragma unroll
    for (int e = 0; e < 4; e++) {
        int idx = tid + e*256;
        int r = idx >> 5, d = idx & 31;
        int qi = qi0 + r, kj = kj0 + r;
        Qs[r][d] = (qi < LL) ? qbase[(size_t)qi*768 + d] : 0.f;
        Ks[r][d] = (kj < LL) ? kbase[(size_t)kj*768 + d] : 0.f;
    }
    __syncthreads();
    int tr = tid >> 4, tc = tid & 15;
    float s00 = 0.f, s01 = 0.f, s10 = 0.f, s11 = 0.f;
    #pragma unroll
    for (int d = 0; d < 32; d++) {
        float q0 = Qs[tr*2][d],   q1 = Qs[tr*2+1][d];
        float k0 = Ks[tc*2][d],   k1 = Ks[tc*2+1][d];
        s00 += q0*k0; s01 += q0*k1;
        s10 += q1*k0; s11 += q1*k1;
    }
    float slope = (h < 4) ? 1.0f : 0.5f;           // slopes = [1,1,1,1,.5,.5,.5,.5]
    const float scale = 0.17677669529663689f;       // 1/sqrt(32)
    float* srow = g_sc + (size_t)g*LL*LL;
    float s[2][2] = {{s00, s01}, {s10, s11}};
    #pragma unroll
    for (int i = 0; i < 2; i++) {
        int qi = qi0 + tr*2 + i;
        if (qi >= LL) continue;
        #pragma unroll
        for (int j = 0; j < 2; j++) {
            int kj = kj0 + tc*2 + j;
            if (kj >= LL) continue;
            srow[(size_t)qi*LL + kj] = s[i][j]*scale - slope * fabsf((float)(qi - kj));
        }
    }
}

// ---------------- row softmax over L ----------------
__global__ __launch_bounds__(128) void k_softmax()
{
    size_t row = blockIdx.x;
    float* p = g_sc + row * LL;
    int tid = threadIdx.x;
    float v[4];
    #pragma unroll
    for (int i = 0; i < 4; i++) {
        int idx = tid + i*128;
        v[i] = (idx < LL) ? p[idx] : -1e30f;
    }
    __shared__ float red[128];
    float m = fmaxf(fmaxf(v[0], v[1]), fmaxf(v[2], v[3]));
    red[tid] = m; __syncthreads();
    for (int s = 64; s > 0; s >>= 1) { if (tid < s) red[tid] = fmaxf(red[tid], red[tid+s]); __syncthreads(); }
    m = red[0]; __syncthreads();
    float sum = 0.f;
    #pragma unroll
    for (int i = 0; i < 4; i++) { v[i] = __expf(v[i] - m); sum += v[i]; }
    red[tid] = sum; __syncthreads();
    for (int s = 64; s > 0; s >>= 1) { if (tid < s) red[tid] += red[tid+s]; __syncthreads(); }
    float inv = 1.0f / red[0];
    #pragma unroll
    for (int i = 0; i < 4; i++) {
        int idx = tid + i*128;
        if (idx < LL) p[idx] = v[i] * inv;
    }
}

// ---------------- out = P @ V ----------------
__global__ __launch_bounds__(256) void k_av()
{
    int g = blockIdx.z;
    int b = g >> 3, h = g & 7;
    int i0 = blockIdx.x * 64;
    __shared__ float Ps[64][32];
    __shared__ float Vs[32][33];
    int tid = threadIdx.x;
    int d = tid & 31, rg = tid >> 5;   // 8 row-groups
    float acc[8] = {};
    const float* srow  = g_sc + (size_t)g*LL*LL;
    const float* vbase = g_qkv + (size_t)b*LL*768 + 2*DD + h*HD;
    for (int j0 = 0; j0 < LL; j0 += 32) {
        #pragma unroll
        for (int e = 0; e < 8; e++) {
            int idx = tid + e*256;
            int i = idx >> 5, jj = idx & 31;
            int qi = i0 + i, j = j0 + jj;
            Ps[i][jj] = (qi < LL && j < LL) ? srow[(size_t)qi*LL + j] : 0.f;
        }
        #pragma unroll
        for (int e = 0; e < 4; e++) {
            int idx = tid + e*256;
            int r = idx >> 5, dd = idx & 31;
            int j = j0 + r;
            Vs[r][dd] = (j < LL) ? vbase[(size_t)j*768 + dd] : 0.f;
        }
        __syncthreads();
        #pragma unroll
        for (int jj = 0; jj < 32; jj++) {
            float vv = Vs[jj][d];
            #pragma unroll
            for (int r = 0; r < 8; r++)
                acc[r] += Ps[rg*8 + r][jj] * vv;
        }
        __syncthreads();
    }
    float* obase = g_tmp + (size_t)b*LL*DD + h*HD;
    #pragma unroll
    for (int r = 0; r < 8; r++) {
        int qi = i0 + rg*8 + r;
        if (qi < LL) obase[(size_t)qi*DD + d] = acc[r];
    }
}

// ---------------- x = LN(x + tmp) ----------------
__global__ __launch_bounds__(256) void k_addln(
    const float* __restrict__ gamma, const float* __restrict__ beta)
{
    int row = blockIdx.x, d = threadIdx.x;
    size_t off = (size_t)row*DD + d;
    float v = g_x[off] + g_tmp[off];
    __shared__ float red[256];
    red[d] = v; __syncthreads();
    for (int s = 128; s > 0; s >>= 1) { if (d < s) red[d] += red[d+s]; __syncthreads(); }
    float mean = red[0] * (1.0f/256.0f);
    __syncthreads();
    float c = v - mean;
    red[d] = c*c; __syncthreads();
    for (int s = 128; s > 0; s >>= 1) { if (d < s) red[d] += red[d+s]; __syncthreads(); }
    float var = red[0] * (1.0f/256.0f);
    g_x[off] = c * rsqrtf(var + 1e-5f) * gamma[d] + beta[d];
}

// ---------------- head: per-row gated score ----------------
__global__ __launch_bounds__(256) void k_head(
    const float* __restrict__ th1_w, const float* __restrict__ th1_b,
    const float* __restrict__ bn_g,  const float* __restrict__ bn_b,
    const float* __restrict__ th2_w, const float* __restrict__ th2_b)
{
    __shared__ float sx[8][256];
    __shared__ float sw1[256*32];
    int tid = threadIdx.x;
    int w = tid >> 5, lane = tid & 31;
    int row0 = blockIdx.x * 8;
    #pragma unroll
    for (int e = 0; e < 32; e++) sw1[tid + e*256] = th1_w[tid + e*256];
    #pragma unroll
    for (int e = 0; e < 8; e++) {
        int idx = tid + e*256;
        int r = idx >> 8, c = idx & 255;
        int row = row0 + r;
        sx[r][c] = (row < MM) ? g_x[(size_t)row*DD + c] : 0.f;
    }
    __syncthreads();
    int row = row0 + w;
    if (row < MM) {
        float acc = th1_b[lane];
        #pragma unroll 8
        for (int k = 0; k < 256; k++) acc += sx[w][k] * sw1[k*32 + lane];
        acc = acc * (bn_g[lane] * rsqrtf(1.0f + 1e-5f)) + bn_b[lane];
        float t = tanhf(0.7978845608028654f * (acc + 0.044715f*acc*acc*acc));
        float ge = 0.5f * acc * (1.0f + t);
        float ps = ge * th2_w[lane];
        #pragma unroll
        for (int s = 16; s > 0; s >>= 1) ps += __shfl_xor_sync(0xffffffffu, ps, s);
        if (lane == 0) g_hsc[row] = ps + th2_b[0];
    }
}

// ---------------- softmax over L + pooled output ----------------
__global__ __launch_bounds__(256) void k_pool(float* __restrict__ out)
{
    int b = blockIdx.x, tid = threadIdx.x;
    __shared__ float wv[LL];
    __shared__ float red[256];
    float v[2];
    #pragma unroll
    for (int i = 0; i < 2; i++) {
        int l = tid + i*256;
        v[i] = (l < LL) ? g_hsc[b*LL + l] : -1e30f;
    }
    float m = fmaxf(v[0], v[1]);
    red[tid] = m; __syncthreads();
    for (int s = 128; s > 0; s >>= 1) { if (tid < s) red[tid] = fmaxf(red[tid], red[tid+s]); __syncthreads(); }
    m = red[0]; __syncthreads();
    float sum = 0.f;
    #pragma unroll
    for (int i = 0; i < 2; i++) { v[i] = __expf(v[i] - m); sum += v[i]; }
    red[tid] = sum; __syncthreads();
    for (int s = 128; s > 0; s >>= 1) { if (tid < s) red[tid] += red[tid+s]; __syncthreads(); }
    float inv = 1.0f / red[0];
    #pragma unroll
    for (int i = 0; i < 2; i++) {
        int l = tid + i*256;
        if (l < LL) wv[l] = v[i] * inv;
    }
    __syncthreads();
    float acc = 0.f;
    const float* xb = g_x + (size_t)b*LL*DD;
    for (int l = 0; l < LL; l++) acc += wv[l] * xb[(size_t)l*DD + tid];
    out[b*DD + tid] = acc;
}

// ---------------- launcher ----------------
extern "C" void kernel_launch(void* const* d_in, const int* in_sizes, int n_in,
                              void* d_out, int out_size)
{
    const float* gene   = (const float*)d_in[0];
    const float* coords = (const float*)d_in[1];
    const float* w_in   = (const float*)d_in[2];
    const float* b_in   = (const float*)d_in[3];
    const float* w_cls  = (const float*)d_in[4];
    const float* b_cls  = (const float*)d_in[5];
    const float* qkv_w  = (const float*)d_in[6];
    const float* qkv_b  = (const float*)d_in[7];
    const float* ln1_g  = (const float*)d_in[8];
    const float* ln1_b  = (const float*)d_in[9];
    const float* ffn_w1 = (const float*)d_in[10];
    const float* ffn_b1 = (const float*)d_in[11];
    const float* ffn_w2 = (const float*)d_in[12];
    const float* ffn_b2 = (const float*)d_in[13];
    const float* ln2_g  = (const float*)d_in[14];
    const float* ln2_b  = (const float*)d_in[15];
    const float* th1_w  = (const float*)d_in[16];
    const float* th1_b  = (const float*)d_in[17];
    const float* bn_g   = (const float*)d_in[18];
    const float* bn_b   = (const float*)d_in[19];
    const float* th2_w  = (const float*)d_in[20];
    const float* th2_b  = (const float*)d_in[21];
    float* out = (float*)d_out;

    k_input<<<BB*LL, 256>>>(gene, coords, w_in, b_in, w_cls, b_cls);

    for (int l = 0; l < NLAYER; l++) {
        // QKV projection: [M,256] @ [256,768]
        k_gemm<<<dim3(768/64, MM/64), 256>>>(0, qkv_w + (size_t)l*DD*3*DD,
                                             qkv_b + (size_t)l*3*DD, 768, DD, 0);
        k_qk<<<dim3(15, 15, BB*HH), 256>>>();
        k_softmax<<<BB*HH*LL, 128>>>();
        k_av<<<dim3(8, 1, BB*HH), 256>>>();
        k_addln<<<MM, 256>>>(ln1_g + (size_t)l*DD, ln1_b + (size_t)l*DD);
        // FFN
        k_gemm<<<dim3(FFD/64, MM/64), 256>>>(1, ffn_w1 + (size_t)l*DD*FFD,
                                             ffn_b1 + (size_t)l*FFD, FFD, DD, 1);
        k_gemm<<<dim3(DD/64, MM/64), 256>>>(2, ffn_w2 + (size_t)l*FFD*DD,
                                            ffn_b2 + (size_t)l*DD, DD, FFD, 0);
        k_addln<<<MM, 256>>>(ln2_g + (size_t)l*DD, ln2_b + (size_t)l*DD);
    }

    k_head<<<(MM + 7)/8, 256>>>(th1_w, th1_b, bn_g, bn_b, th2_w, th2_b);
    k_pool<<<BB, 256>>>(out);
}

// round 3
// speedup vs baseline: 1.2554x; 1.2554x over previous
#include <cuda_runtime.h>
#include <math.h>

#define BB 64
#define TOK 64
#define NTK 456
#define LL 457
#define DD 256
#define HH 8
#define HD 32
#define NLAYER 4
#define FFD 1024
#define MM (BB*LL)          // 29248
#define MMP 29312           // padded to multiple of 128

// ---------------- device scratch ----------------
__device__ float g_x   [(size_t)MMP*DD];
__device__ float g_tmp [(size_t)MMP*DD];
__device__ float g_qkv [(size_t)MMP*3*DD];
__device__ float g_ffh [(size_t)MMP*FFD];
__device__ float g_hsc [MM];

// ---------------- input projection + CLS ----------------
__global__ __launch_bounds__(256) void k_input(
    const float* __restrict__ gene, const float* __restrict__ coords,
    const float* __restrict__ w_in, const float* __restrict__ b_in,
    const float* __restrict__ w_cls, const float* __restrict__ b_cls)
{
    int row = blockIdx.x;
    int b = row / LL, l = row % LL;
    int d = threadIdx.x;
    if (l == 0) {
        float acc = b_cls[d];
        #pragma unroll
        for (int k = 0; k < 3; k++) acc += coords[b*3 + k] * w_cls[k*DD + d];
        g_x[(size_t)row*DD + d] = acc;
    } else {
        __shared__ float sg[TOK];
        if (d < TOK) sg[d] = gene[(size_t)b*(NTK*TOK) + (size_t)(l-1)*TOK + d];
        __syncthreads();
        float acc = b_in[d];
        #pragma unroll 8
        for (int k = 0; k < TOK; k++) acc += sg[k] * w_in[k*DD + d];
        g_x[(size_t)row*DD + d] = acc;
    }
}

// ---------------- tiled SGEMM 128x64, 8x4 microtile ----------------
// sel: 0: A=g_x C=g_qkv   1: A=g_x C=g_ffh   2: A=g_ffh C=g_tmp
__global__ __launch_bounds__(256) void k_gemm(
    int sel, const float* __restrict__ W, const float* __restrict__ bias,
    int N, int K, int relu)
{
    const float* A; float* C;
    if (sel == 0)      { A = g_x;   C = g_qkv; }
    else if (sel == 1) { A = g_x;   C = g_ffh; }
    else               { A = g_ffh; C = g_tmp; }

    __shared__ float As[16][132];   // [k][m], pitch mult of 4
    __shared__ float Bs[16][68];    // [k][n]
    int tid = threadIdx.x;
    int tr = tid >> 4, tc = tid & 15;
    int bm = blockIdx.y * 128, bn = blockIdx.x * 64;
    float acc[8][4] = {};
    const float* Ab = A + (size_t)bm * K;

    for (int k0 = 0; k0 < K; k0 += 16) {
        #pragma unroll
        for (int e = 0; e < 8; e++) {
            int idx = tid + e*256;
            int r = idx >> 4, c = idx & 15;
            As[c][r] = Ab[(size_t)r*K + k0 + c];
        }
        #pragma unroll
        for (int e = 0; e < 4; e++) {
            int idx = tid + e*256;
            int kk = idx >> 6, n = idx & 63;
            Bs[kk][n] = W[(size_t)(k0+kk)*N + bn + n];
        }
        __syncthreads();
        #pragma unroll
        for (int kk = 0; kk < 16; kk++) {
            float4 a0 = *reinterpret_cast<const float4*>(&As[kk][8*tr]);
            float4 a1 = *reinterpret_cast<const float4*>(&As[kk][8*tr+4]);
            float4 bv = *reinterpret_cast<const float4*>(&Bs[kk][4*tc]);
            float a[8] = {a0.x,a0.y,a0.z,a0.w,a1.x,a1.y,a1.z,a1.w};
            float b[4] = {bv.x,bv.y,bv.z,bv.w};
            #pragma unroll
            for (int i = 0; i < 8; i++)
                #pragma unroll
                for (int j = 0; j < 4; j++)
                    acc[i][j] += a[i] * b[j];
        }
        __syncthreads();
    }
    #pragma unroll
    for (int i = 0; i < 8; i++) {
        size_t r = bm + 8*tr + i;
        #pragma unroll
        for (int j = 0; j < 4; j++) {
            int c = bn + 4*tc + j;
            float v = acc[i][j] + bias[c];
            if (relu) v = fmaxf(v, 0.f);
            C[r*N + c] = v;
        }
    }
}

// ---------------- fused flash attention ----------------
// block: (qtile of 64 rows) x (b,h). 256 threads, tr=tid>>4 (16 row-groups of 4),
// tc=tid&15 (16 col-groups). S microtile 4x4; O microtile 4x2.
__global__ __launch_bounds__(256) void k_attn()
{
    __shared__ float Qs[32][68];   // [d][q]
    __shared__ float Ks[32][68];   // [d][j]
    __shared__ float Vs[64][34];   // [j][d]
    __shared__ float Ps[64][68];   // [q][j]

    int g = blockIdx.y;
    int b = g >> 3, h = g & 7;
    int qi0 = blockIdx.x * 64;
    int tid = threadIdx.x;
    int tr = tid >> 4, tc = tid & 15;

    const float* qbase = g_qkv + (size_t)b*LL*768 + h*HD;
    const float* kbase = qbase + DD;
    const float* vbase = qbase + 2*DD;

    // load Q tile (transposed)
    #pragma unroll
    for (int e = 0; e < 8; e++) {
        int idx = tid + e*256;
        int r = idx >> 5, d = idx & 31;
        int qi = qi0 + r;
        Qs[d][r] = (qi < LL) ? qbase[(size_t)qi*768 + d] : 0.f;
    }

    float o[4][2] = {};
    float m_run[4] = {-1e30f, -1e30f, -1e30f, -1e30f};
    float s_run[4] = {};
    const float slope = (h < 4) ? 1.0f : 0.5f;
    const float scale = 0.17677669529663689f;   // 1/sqrt(32)

    for (int j0 = 0; j0 < LL; j0 += 64) {
        __syncthreads();   // protect Ks/Vs/Ps from previous iteration's readers
        #pragma unroll
        for (int e = 0; e < 8; e++) {
            int idx = tid + e*256;
            int r = idx >> 5, d = idx & 31;
            int j = j0 + r;
            bool ok = (j < LL);
            Ks[d][r] = ok ? kbase[(size_t)j*768 + d] : 0.f;
            Vs[r][d] = ok ? vbase[(size_t)j*768 + d] : 0.f;
        }
        __syncthreads();

        // S = Q @ K^T  (4x4 per thread)
        float s[4][4] = {};
        #pragma unroll
        for (int d = 0; d < 32; d++) {
            float4 qv = *reinterpret_cast<const float4*>(&Qs[d][4*tr]);
            float4 kv = *reinterpret_cast<const float4*>(&Ks[d][4*tc]);
            float q[4] = {qv.x,qv.y,qv.z,qv.w};
            float k[4] = {kv.x,kv.y,kv.z,kv.w};
            #pragma unroll
            for (int i = 0; i < 4; i++)
                #pragma unroll
                for (int j = 0; j < 4; j++)
                    s[i][j] += q[i] * k[j];
        }
        // scale + alibi + mask
        #pragma unroll
        for (int i = 0; i < 4; i++) {
            int qi = qi0 + 4*tr + i;
            #pragma unroll
            for (int j = 0; j < 4; j++) {
                int kj = j0 + 4*tc + j;
                s[i][j] = (kj < LL)
                    ? s[i][j]*scale - slope * fabsf((float)(qi - kj))
                    : -1e30f;
            }
        }
        // online softmax (row groups of 16 threads = same tr)
        #pragma unroll
        for (int i = 0; i < 4; i++) {
            float mloc = fmaxf(fmaxf(s[i][0], s[i][1]), fmaxf(s[i][2], s[i][3]));
            #pragma unroll
            for (int off = 8; off > 0; off >>= 1)
                mloc = fmaxf(mloc, __shfl_xor_sync(0xffffffffu, mloc, off));
            float m_new = fmaxf(m_run[i], mloc);
            float corr = __expf(m_run[i] - m_new);
            float rs = 0.f;
            #pragma unroll
            for (int j = 0; j < 4; j++) { s[i][j] = __expf(s[i][j] - m_new); rs += s[i][j]; }
            #pragma unroll
            for (int off = 8; off > 0; off >>= 1)
                rs += __shfl_xor_sync(0xffffffffu, rs, off);
            s_run[i] = s_run[i]*corr + rs;
            m_run[i] = m_new;
            o[i][0] *= corr; o[i][1] *= corr;
        }
        // write P (row-major, float4 stores)
        #pragma unroll
        for (int i = 0; i < 4; i++) {
            float4 pv = make_float4(s[i][0], s[i][1], s[i][2], s[i][3]);
            *reinterpret_cast<float4*>(&Ps[4*tr + i][4*tc]) = pv;
        }
        __syncthreads();

        // O += P @ V (4 rows x 2 d-cols per thread)
        #pragma unroll 4
        for (int j = 0; j < 64; j++) {
            float v0 = Vs[j][2*tc];
            float v1 = Vs[j][2*tc + 1];
            #pragma unroll
            for (int i = 0; i < 4; i++) {
                float p = Ps[4*tr + i][j];
                o[i][0] += p * v0;
                o[i][1] += p * v1;
            }
        }
    }

    float* obase = g_tmp + (size_t)b*LL*DD + h*HD;
    #pragma unroll
    for (int i = 0; i < 4; i++) {
        int qi = qi0 + 4*tr + i;
        if (qi < LL) {
            float inv = 1.0f / s_run[i];
            obase[(size_t)qi*DD + 2*tc]     = o[i][0] * inv;
            obase[(size_t)qi*DD + 2*tc + 1] = o[i][1] * inv;
        }
    }
}

// ---------------- x = LN(x + tmp) ----------------
__global__ __launch_bounds__(256) void k_addln(
    const float* __restrict__ gamma, const float* __restrict__ beta)
{
    int row = blockIdx.x, d = threadIdx.x;
    size_t off = (size_t)row*DD + d;
    float v = g_x[off] + g_tmp[off];
    __shared__ float red[256];
    red[d] = v; __syncthreads();
    for (int s = 128; s > 0; s >>= 1) { if (d < s) red[d] += red[d+s]; __syncthreads(); }
    float mean = red[0] * (1.0f/256.0f);
    __syncthreads();
    float c = v - mean;
    red[d] = c*c; __syncthreads();
    for (int s = 128; s > 0; s >>= 1) { if (d < s) red[d] += red[d+s]; __syncthreads(); }
    float var = red[0] * (1.0f/256.0f);
    g_x[off] = c * rsqrtf(var + 1e-5f) * gamma[d] + beta[d];
}

// ---------------- head ----------------
__global__ __launch_bounds__(256) void k_head(
    const float* __restrict__ th1_w, const float* __restrict__ th1_b,
    const float* __restrict__ bn_g,  const float* __restrict__ bn_b,
    const float* __restrict__ th2_w, const float* __restrict__ th2_b)
{
    __shared__ float sx[8][256];
    __shared__ float sw1[256*32];
    int tid = threadIdx.x;
    int w = tid >> 5, lane = tid & 31;
    int row0 = blockIdx.x * 8;
    #pragma unroll
    for (int e = 0; e < 32; e++) sw1[tid + e*256] = th1_w[tid + e*256];
    #pragma unroll
    for (int e = 0; e < 8; e++) {
        int idx = tid + e*256;
        int r = idx >> 8, c = idx & 255;
        int row = row0 + r;
        sx[r][c] = (row < MM) ? g_x[(size_t)row*DD + c] : 0.f;
    }
    __syncthreads();
    int row = row0 + w;
    if (row < MM) {
        float acc = th1_b[lane];
        #pragma unroll 8
        for (int k = 0; k < 256; k++) acc += sx[w][k] * sw1[k*32 + lane];
        acc = acc * (bn_g[lane] * rsqrtf(1.0f + 1e-5f)) + bn_b[lane];
        float t = tanhf(0.7978845608028654f * (acc + 0.044715f*acc*acc*acc));
        float ge = 0.5f * acc * (1.0f + t);
        float ps = ge * th2_w[lane];
        #pragma unroll
        for (int s = 16; s > 0; s >>= 1) ps += __shfl_xor_sync(0xffffffffu, ps, s);
        if (lane == 0) g_hsc[row] = ps + th2_b[0];
    }
}

// ---------------- softmax over L + pooled output ----------------
__global__ __launch_bounds__(256) void k_pool(float* __restrict__ out)
{
    int b = blockIdx.x, tid = threadIdx.x;
    __shared__ float wv[LL];
    __shared__ float red[256];
    float v[2];
    #pragma unroll
    for (int i = 0; i < 2; i++) {
        int l = tid + i*256;
        v[i] = (l < LL) ? g_hsc[b*LL + l] : -1e30f;
    }
    float m = fmaxf(v[0], v[1]);
    red[tid] = m; __syncthreads();
    for (int s = 128; s > 0; s >>= 1) { if (tid < s) red[tid] = fmaxf(red[tid], red[tid+s]); __syncthreads(); }
    m = red[0]; __syncthreads();
    float sum = 0.f;
    #pragma unroll
    for (int i = 0; i < 2; i++) { v[i] = __expf(v[i] - m); sum += v[i]; }
    red[tid] = sum; __syncthreads();
    for (int s = 128; s > 0; s >>= 1) { if (tid < s) red[tid] += red[tid+s]; __syncthreads(); }
    float inv = 1.0f / red[0];
    #pragma unroll
    for (int i = 0; i < 2; i++) {
        int l = tid + i*256;
        if (l < LL) wv[l] = v[i] * inv;
    }
    __syncthreads();
    float acc = 0.f;
    const float* xb = g_x + (size_t)b*LL*DD;
    for (int l = 0; l < LL; l++) acc += wv[l] * xb[(size_t)l*DD + tid];
    out[b*DD + tid] = acc;
}

// ---------------- launcher ----------------
extern "C" void kernel_launch(void* const* d_in, const int* in_sizes, int n_in,
                              void* d_out, int out_size)
{
    const float* gene   = (const float*)d_in[0];
    const float* coords = (const float*)d_in[1];
    const float* w_in   = (const float*)d_in[2];
    const float* b_in   = (const float*)d_in[3];
    const float* w_cls  = (const float*)d_in[4];
    const float* b_cls  = (const float*)d_in[5];
    const float* qkv_w  = (const float*)d_in[6];
    const float* qkv_b  = (const float*)d_in[7];
    const float* ln1_g  = (const float*)d_in[8];
    const float* ln1_b  = (const float*)d_in[9];
    const float* ffn_w1 = (const float*)d_in[10];
    const float* ffn_b1 = (const float*)d_in[11];
    const float* ffn_w2 = (const float*)d_in[12];
    const float* ffn_b2 = (const float*)d_in[13];
    const float* ln2_g  = (const float*)d_in[14];
    const float* ln2_b  = (const float*)d_in[15];
    const float* th1_w  = (const float*)d_in[16];
    const float* th1_b  = (const float*)d_in[17];
    const float* bn_g   = (const float*)d_in[18];
    const float* bn_b   = (const float*)d_in[19];
    const float* th2_w  = (const float*)d_in[20];
    const float* th2_b  = (const float*)d_in[21];
    float* out = (float*)d_out;

    k_input<<<BB*LL, 256>>>(gene, coords, w_in, b_in, w_cls, b_cls);

    for (int l = 0; l < NLAYER; l++) {
        k_gemm<<<dim3(768/64, MMP/128), 256>>>(0, qkv_w + (size_t)l*DD*3*DD,
                                               qkv_b + (size_t)l*3*DD, 768, DD, 0);
        k_attn<<<dim3(8, BB*HH), 256>>>();
        k_addln<<<MM, 256>>>(ln1_g + (size_t)l*DD, ln1_b + (size_t)l*DD);
        k_gemm<<<dim3(FFD/64, MMP/128), 256>>>(1, ffn_w1 + (size_t)l*DD*FFD,
                                               ffn_b1 + (size_t)l*FFD, FFD, DD, 1);
        k_gemm<<<dim3(DD/64, MMP/128), 256>>>(2, ffn_w2 + (size_t)l*FFD*DD,
                                              ffn_b2 + (size_t)l*DD, DD, FFD, 0);
        k_addln<<<MM, 256>>>(ln2_g + (size_t)l*DD, ln2_b + (size_t)l*DD);
    }

    k_head<<<(MM + 7)/8, 256>>>(th1_w, th1_b, bn_g, bn_b, th2_w, th2_b);
    k_pool<<<BB, 256>>>(out);
}

// round 4
// speedup vs baseline: 1.9361x; 1.5422x over previous
#include <cuda_runtime.h>
#include <cuda_bf16.h>
#include <math.h>
#include <stdint.h>

#define BB 64
#define TOK 64
#define NTK 456
#define LL 457
#define DD 256
#define HH 8
#define HD 32
#define NLAYER 4
#define FFD 1024
#define MM (BB*LL)          // 29248
#define MMP 29312           // padded to multiple of 128

#define WSTRIDE 720896      // per-layer elems in split weight buffer
#define OFF_QKV 0
#define OFF_FF1 196608
#define OFF_FF2 458752

// ---------------- device scratch ----------------
__device__ float g_x   [(size_t)MMP*DD];
__device__ float g_tmp [(size_t)MMP*DD];
__device__ float g_qkv [(size_t)MMP*3*DD];
__device__ float g_hsc [MM];
// bf16 hi/lo planes
__device__ __nv_bfloat16 g_xh[(size_t)MMP*DD],  g_xl[(size_t)MMP*DD];
__device__ __nv_bfloat16 g_fh[(size_t)MMP*FFD], g_fl[(size_t)MMP*FFD];
__device__ __nv_bfloat16 g_wh[(size_t)NLAYER*WSTRIDE], g_wl[(size_t)NLAYER*WSTRIDE];

// ---------------- helpers ----------------
__device__ __forceinline__ void bsplit2(float a, float b,
                                        __nv_bfloat162& hi, __nv_bfloat162& lo)
{
    hi = __floats2bfloat162_rn(a, b);
    lo = __floats2bfloat162_rn(a - __bfloat162float(hi.x),
                               b - __bfloat162float(hi.y));
}

#define MMA16816(d, a0,a1,a2,a3, b0,b1) \
  asm volatile("mma.sync.aligned.m16n8k16.row.col.f32.bf16.bf16.f32 " \
    "{%0,%1,%2,%3}, {%4,%5,%6,%7}, {%8,%9}, {%0,%1,%2,%3};\n" \
    : "+f"(d[0]), "+f"(d[1]), "+f"(d[2]), "+f"(d[3]) \
    : "r"(a0), "r"(a1), "r"(a2), "r"(a3), "r"(b0), "r"(b1))

// ---------------- weight split + transpose: W[K][N] -> Wt planes [N][K] ----------------
__global__ __launch_bounds__(256) void k_wsplit(
    const float* __restrict__ W, int K, int N, size_t out_base)
{
    __shared__ float t[32][33];
    int l = blockIdx.z;
    const float* Wp = W + (size_t)l*K*N;
    int n0 = blockIdx.x*32, k0 = blockIdx.y*32;
    int tx = threadIdx.x & 31, ty = threadIdx.x >> 5;
    #pragma unroll
    for (int i = ty; i < 32; i += 8)
        t[i][tx] = Wp[(size_t)(k0+i)*N + n0 + tx];
    __syncthreads();
    #pragma unroll
    for (int i = ty; i < 32; i += 8) {
        float v = t[tx][i];   // = W[k0+tx][n0+i]
        size_t o = out_base + (size_t)l*WSTRIDE + (size_t)(n0+i)*K + (k0+tx);
        __nv_bfloat16 h = __float2bfloat16(v);
        g_wh[o] = h;
        g_wl[o] = __float2bfloat16(v - __bfloat162float(h));
    }
}

// ---------------- input projection + CLS (also emits bf16 planes) ----------------
__global__ __launch_bounds__(256) void k_input(
    const float* __restrict__ gene, const float* __restrict__ coords,
    const float* __restrict__ w_in, const float* __restrict__ b_in,
    const float* __restrict__ w_cls, const float* __restrict__ b_cls)
{
    int row = blockIdx.x;
    int b = row / LL, l = row % LL;
    int d = threadIdx.x;
    size_t off = (size_t)row*DD + d;
    float acc;
    if (l == 0) {
        acc = b_cls[d];
        #pragma unroll
        for (int k = 0; k < 3; k++) acc += coords[b*3 + k] * w_cls[k*DD + d];
    } else {
        __shared__ float sg[TOK];
        if (d < TOK) sg[d] = gene[(size_t)b*(NTK*TOK) + (size_t)(l-1)*TOK + d];
        __syncthreads();
        acc = b_in[d];
        #pragma unroll 8
        for (int k = 0; k < TOK; k++) acc += sg[k] * w_in[k*DD + d];
    }
    g_x[off] = acc;
    __nv_bfloat16 h = __float2bfloat16(acc);
    g_xh[off] = h;
    g_xl[off] = __float2bfloat16(acc - __bfloat162float(h));
}

// ---------------- bf16x3 tensor-core GEMM ----------------
// C[M,N] = A[M,K] @ W[K,N] + bias. Block tile 128x64, warp tile 32x32, KB=32.
// sel 0: A=x planes,  C=g_qkv fp32            (N=768, K=256)
// sel 1: A=x planes,  C=relu -> ffh planes     (N=1024,K=256)
// sel 2: A=ffh planes,C=g_tmp fp32            (N=256, K=1024)
__global__ __launch_bounds__(256) void k_gemm_mma(
    int sel, size_t woff, const float* __restrict__ bias, int N, int K)
{
    __shared__ uint32_t AshH[128*20], AshL[128*20];   // [m][k-pair], pitch 20 words
    __shared__ uint32_t BshH[64*20],  BshL[64*20];    // [n][k-pair]

    const __nv_bfloat16 *Ah, *Al;
    if (sel == 2) { Ah = g_fh; Al = g_fl; }
    else          { Ah = g_xh; Al = g_xl; }

    int tid = threadIdx.x;
    int wid = tid >> 5, lane = tid & 31;
    int g = lane >> 2, c = lane & 3;
    int wm = wid & 3, wn = wid >> 2;
    int bm = blockIdx.y * 128, bn = blockIdx.x * 64;

    float acc[2][4][4] = {};

    for (int k0 = 0; k0 < K; k0 += 32) {
        // load A tile 128x32, both planes (uint4 = 8 bf16)
        #pragma unroll
        for (int e = 0; e < 2; e++) {
            int idx = tid + e*256;          // 0..511
            int m = idx >> 2, q = idx & 3;
            size_t go = (size_t)(bm+m)*K + k0 + q*8;
            *reinterpret_cast<uint4*>(AshH + m*20 + q*4) =
                *reinterpret_cast<const uint4*>(Ah + go);
            *reinterpret_cast<uint4*>(AshL + m*20 + q*4) =
                *reinterpret_cast<const uint4*>(Al + go);
        }
        // load B tile 64x32 (transposed weights [N][K]), both planes
        {
            int n = tid >> 2, q = tid & 3;
            size_t go = woff + (size_t)(bn+n)*K + k0 + q*8;
            *reinterpret_cast<uint4*>(BshH + n*20 + q*4) =
                *reinterpret_cast<const uint4*>(g_wh + go);
            *reinterpret_cast<uint4*>(BshL + n*20 + q*4) =
                *reinterpret_cast<const uint4*>(g_wl + go);
        }
        __syncthreads();

        #pragma unroll
        for (int ks = 0; ks < 2; ks++) {
            uint32_t ah[2][4], al[2][4], bh[4][2], bl[4][2];
            #pragma unroll
            for (int mt = 0; mt < 2; mt++) {
                int m = wm*32 + mt*16 + g;
                int w0 = m*20 + ks*8 + c;
                int w1 = (m+8)*20 + ks*8 + c;
                ah[mt][0] = AshH[w0];   ah[mt][1] = AshH[w1];
                ah[mt][2] = AshH[w0+4]; ah[mt][3] = AshH[w1+4];
                al[mt][0] = AshL[w0];   al[mt][1] = AshL[w1];
                al[mt][2] = AshL[w0+4]; al[mt][3] = AshL[w1+4];
            }
            #pragma unroll
            for (int nt = 0; nt < 4; nt++) {
                int n = wn*32 + nt*8 + g;
                int w0 = n*20 + ks*8 + c;
                bh[nt][0] = BshH[w0]; bh[nt][1] = BshH[w0+4];
                bl[nt][0] = BshL[w0]; bl[nt][1] = BshL[w0+4];
            }
            #pragma unroll
            for (int mt = 0; mt < 2; mt++)
                #pragma unroll
                for (int nt = 0; nt < 4; nt++) {
                    MMA16816(acc[mt][nt], ah[mt][0],ah[mt][1],ah[mt][2],ah[mt][3],
                             bh[nt][0], bh[nt][1]);
                    MMA16816(acc[mt][nt], ah[mt][0],ah[mt][1],ah[mt][2],ah[mt][3],
                             bl[nt][0], bl[nt][1]);
                    MMA16816(acc[mt][nt], al[mt][0],al[mt][1],al[mt][2],al[mt][3],
                             bh[nt][0], bh[nt][1]);
                }
        }
        __syncthreads();
    }

    // epilogue
    #pragma unroll
    for (int mt = 0; mt < 2; mt++) {
        int r0 = bm + wm*32 + mt*16 + g;
        #pragma unroll
        for (int nt = 0; nt < 4; nt++) {
            int cb = bn + wn*32 + nt*8 + 2*c;
            float2 bv = *reinterpret_cast<const float2*>(&bias[cb]);
            float v00 = acc[mt][nt][0] + bv.x, v01 = acc[mt][nt][1] + bv.y;
            float v10 = acc[mt][nt][2] + bv.x, v11 = acc[mt][nt][3] + bv.y;
            size_t o0 = (size_t)r0*N + cb;
            size_t o1 = (size_t)(r0+8)*N + cb;
            if (sel == 1) {
                v00 = fmaxf(v00, 0.f); v01 = fmaxf(v01, 0.f);
                v10 = fmaxf(v10, 0.f); v11 = fmaxf(v11, 0.f);
                __nv_bfloat162 hi, lo;
                bsplit2(v00, v01, hi, lo);
                *reinterpret_cast<__nv_bfloat162*>(g_fh + o0) = hi;
                *reinterpret_cast<__nv_bfloat162*>(g_fl + o0) = lo;
                bsplit2(v10, v11, hi, lo);
                *reinterpret_cast<__nv_bfloat162*>(g_fh + o1) = hi;
                *reinterpret_cast<__nv_bfloat162*>(g_fl + o1) = lo;
            } else {
                float* C = (sel == 0) ? g_qkv : g_tmp;
                *reinterpret_cast<float2*>(C + o0) = make_float2(v00, v01);
                *reinterpret_cast<float2*>(C + o1) = make_float2(v10, v11);
            }
        }
    }
}

// ---------------- fused flash attention (fp32, transposed-P PV loop) ----------------
__global__ __launch_bounds__(256) void k_attn()
{
    __shared__ float Qs[32][68];   // [d][q]
    __shared__ float Ks[32][68];   // [d][j]
    __shared__ float Vs[64][34];   // [j][d]
    __shared__ float Pt[64][68];   // [j][q]  (transposed P)

    int g = blockIdx.y;
    int b = g >> 3, h = g & 7;
    int qi0 = blockIdx.x * 64;
    int tid = threadIdx.x;
    int tr = tid >> 4, tc = tid & 15;

    const float* qbase = g_qkv + (size_t)b*LL*768 + h*HD;
    const float* kbase = qbase + DD;
    const float* vbase = qbase + 2*DD;

    #pragma unroll
    for (int e = 0; e < 8; e++) {
        int idx = tid + e*256;
        int r = idx >> 5, d = idx & 31;
        int qi = qi0 + r;
        Qs[d][r] = (qi < LL) ? qbase[(size_t)qi*768 + d] : 0.f;
    }

    float o[4][2] = {};
    float m_run[4] = {-1e30f, -1e30f, -1e30f, -1e30f};
    float s_run[4] = {};
    const float slope = (h < 4) ? 1.0f : 0.5f;
    const float scale = 0.17677669529663689f;   // 1/sqrt(32)

    for (int j0 = 0; j0 < LL; j0 += 64) {
        __syncthreads();
        #pragma unroll
        for (int e = 0; e < 8; e++) {
            int idx = tid + e*256;
            int r = idx >> 5, d = idx & 31;
            int j = j0 + r;
            bool ok = (j < LL);
            Ks[d][r] = ok ? kbase[(size_t)j*768 + d] : 0.f;
            Vs[r][d] = ok ? vbase[(size_t)j*768 + d] : 0.f;
        }
        __syncthreads();

        float s[4][4] = {};
        #pragma unroll
        for (int d = 0; d < 32; d++) {
            float4 qv = *reinterpret_cast<const float4*>(&Qs[d][4*tr]);
            float4 kv = *reinterpret_cast<const float4*>(&Ks[d][4*tc]);
            float q[4] = {qv.x,qv.y,qv.z,qv.w};
            float k[4] = {kv.x,kv.y,kv.z,kv.w};
            #pragma unroll
            for (int i = 0; i < 4; i++)
                #pragma unroll
                for (int j = 0; j < 4; j++)
                    s[i][j] += q[i] * k[j];
        }
        #pragma unroll
        for (int i = 0; i < 4; i++) {
            int qi = qi0 + 4*tr + i;
            #pragma unroll
            for (int j = 0; j < 4; j++) {
                int kj = j0 + 4*tc + j;
                s[i][j] = (kj < LL)
                    ? s[i][j]*scale - slope * fabsf((float)(qi - kj))
                    : -1e30f;
            }
        }
        #pragma unroll
        for (int i = 0; i < 4; i++) {
            float mloc = fmaxf(fmaxf(s[i][0], s[i][1]), fmaxf(s[i][2], s[i][3]));
            #pragma unroll
            for (int off = 8; off > 0; off >>= 1)
                mloc = fmaxf(mloc, __shfl_xor_sync(0xffffffffu, mloc, off));
            float m_new = fmaxf(m_run[i], mloc);
            float corr = __expf(m_run[i] - m_new);
            float rs = 0.f;
            #pragma unroll
            for (int j = 0; j < 4; j++) { s[i][j] = __expf(s[i][j] - m_new); rs += s[i][j]; }
            #pragma unroll
            for (int off = 8; off > 0; off >>= 1)
                rs += __shfl_xor_sync(0xffffffffu, rs, off);
            s_run[i] = s_run[i]*corr + rs;
            m_run[i] = m_new;
            o[i][0] *= corr; o[i][1] *= corr;
        }
        // store P transposed: Pt[j][q]
        #pragma unroll
        for (int jj = 0; jj < 4; jj++) {
            float4 pv = make_float4(s[0][jj], s[1][jj], s[2][jj], s[3][jj]);
            *reinterpret_cast<float4*>(&Pt[4*tc + jj][4*tr]) = pv;
        }
        __syncthreads();

        // O += P @ V : per j, 1 LDS.128 + 1 LDS.64 per 8 FFMA
        #pragma unroll 4
        for (int j = 0; j < 64; j++) {
            float2 v = *reinterpret_cast<const float2*>(&Vs[j][2*tc]);
            float4 p = *reinterpret_cast<const float4*>(&Pt[j][4*tr]);
            o[0][0] += p.x*v.x; o[0][1] += p.x*v.y;
            o[1][0] += p.y*v.x; o[1][1] += p.y*v.y;
            o[2][0] += p.z*v.x; o[2][1] += p.z*v.y;
            o[3][0] += p.w*v.x; o[3][1] += p.w*v.y;
        }
    }

    float* obase = g_tmp + (size_t)b*LL*DD + h*HD;
    #pragma unroll
    for (int i = 0; i < 4; i++) {
        int qi = qi0 + 4*tr + i;
        if (qi < LL) {
            float inv = 1.0f / s_run[i];
            obase[(size_t)qi*DD + 2*tc]     = o[i][0] * inv;
            obase[(size_t)qi*DD + 2*tc + 1] = o[i][1] * inv;
        }
    }
}

// ---------------- x = LN(x + tmp), warp-per-row, optional bf16 plane emit ----------------
__global__ __launch_bounds__(256) void k_addln(
    const float* __restrict__ gamma, const float* __restrict__ beta, int planes)
{
    int w = threadIdx.x >> 5, lane = threadIdx.x & 31;
    int row = blockIdx.x*8 + w;
    size_t base = (size_t)row*DD + lane*4;

    float4 a0 = *reinterpret_cast<const float4*>(&g_x[base]);
    float4 a1 = *reinterpret_cast<const float4*>(&g_x[base+128]);
    float4 t0 = *reinterpret_cast<const float4*>(&g_tmp[base]);
    float4 t1 = *reinterpret_cast<const float4*>(&g_tmp[base+128]);
    float v[8] = {a0.x+t0.x, a0.y+t0.y, a0.z+t0.z, a0.w+t0.w,
                  a1.x+t1.x, a1.y+t1.y, a1.z+t1.z, a1.w+t1.w};
    float s = 0.f, s2 = 0.f;
    #pragma unroll
    for (int i = 0; i < 8; i++) { s += v[i]; s2 += v[i]*v[i]; }
    #pragma unroll
    for (int off = 16; off > 0; off >>= 1) {
        s  += __shfl_xor_sync(0xffffffffu, s,  off);
        s2 += __shfl_xor_sync(0xffffffffu, s2, off);
    }
    float mean = s * (1.0f/256.0f);
    float var  = s2 * (1.0f/256.0f) - mean*mean;
    float inv  = rsqrtf(var + 1e-5f);

    float4 gg0 = *reinterpret_cast<const float4*>(&gamma[lane*4]);
    float4 gg1 = *reinterpret_cast<const float4*>(&gamma[128 + lane*4]);
    float4 bb0 = *reinterpret_cast<const float4*>(&beta[lane*4]);
    float4 bb1 = *reinterpret_cast<const float4*>(&beta[128 + lane*4]);
    float gv[8] = {gg0.x,gg0.y,gg0.z,gg0.w, gg1.x,gg1.y,gg1.z,gg1.w};
    float bv[8] = {bb0.x,bb0.y,bb0.z,bb0.w, bb1.x,bb1.y,bb1.z,bb1.w};
    float y[8];
    #pragma unroll
    for (int i = 0; i < 8; i++) y[i] = (v[i]-mean)*inv*gv[i] + bv[i];

    *reinterpret_cast<float4*>(&g_x[base])     = make_float4(y[0],y[1],y[2],y[3]);
    *reinterpret_cast<float4*>(&g_x[base+128]) = make_float4(y[4],y[5],y[6],y[7]);
    if (planes) {
        #pragma unroll
        for (int p = 0; p < 4; p++) {
            size_t o = base + (p>>1)*128 + (p&1)*2;
            int i = p*2;
            __nv_bfloat162 hi, lo;
            bsplit2(y[i], y[i+1], hi, lo);
            *reinterpret_cast<__nv_bfloat162*>(g_xh + o) = hi;
            *reinterpret_cast<__nv_bfloat162*>(g_xl + o) = lo;
        }
    }
}

// ---------------- head ----------------
__global__ __launch_bounds__(256) void k_head(
    const float* __restrict__ th1_w, const float* __restrict__ th1_b,
    const float* __restrict__ bn_g,  const float* __restrict__ bn_b,
    const float* __restrict__ th2_w, const float* __restrict__ th2_b)
{
    __shared__ float sx[8][256];
    __shared__ float sw1[256*32];
    int tid = threadIdx.x;
    int w = tid >> 5, lane = tid & 31;
    int row0 = blockIdx.x * 8;
    #pragma unroll
    for (int e = 0; e < 32; e++) sw1[tid + e*256] = th1_w[tid + e*256];
    #pragma unroll
    for (int e = 0; e < 8; e++) {
        int idx = tid + e*256;
        int r = idx >> 8, c = idx & 255;
        int row = row0 + r;
        sx[r][c] = (row < MM) ? g_x[(size_t)row*DD + c] : 0.f;
    }
    __syncthreads();
    int row = row0 + w;
    if (row < MM) {
        float acc = th1_b[lane];
        #pragma unroll 8
        for (int k = 0; k < 256; k++) acc += sx[w][k] * sw1[k*32 + lane];
        acc = acc * (bn_g[lane] * rsqrtf(1.0f + 1e-5f)) + bn_b[lane];
        float t = tanhf(0.7978845608028654f * (acc + 0.044715f*acc*acc*acc));
        float ge = 0.5f * acc * (1.0f + t);
        float ps = ge * th2_w[lane];
        #pragma unroll
        for (int s = 16; s > 0; s >>= 1) ps += __shfl_xor_sync(0xffffffffu, ps, s);
        if (lane == 0) g_hsc[row] = ps + th2_b[0];
    }
}

// ---------------- softmax over L + pooled output ----------------
__global__ __launch_bounds__(256) void k_pool(float* __restrict__ out)
{
    int b = blockIdx.x, tid = threadIdx.x;
    __shared__ float wv[LL];
    __shared__ float red[256];
    float v[2];
    #pragma unroll
    for (int i = 0; i < 2; i++) {
        int l = tid + i*256;
        v[i] = (l < LL) ? g_hsc[b*LL + l] : -1e30f;
    }
    float m = fmaxf(v[0], v[1]);
    red[tid] = m; __syncthreads();
    for (int s = 128; s > 0; s >>= 1) { if (tid < s) red[tid] = fmaxf(red[tid], red[tid+s]); __syncthreads(); }
    m = red[0]; __syncthreads();
    float sum = 0.f;
    #pragma unroll
    for (int i = 0; i < 2; i++) { v[i] = __expf(v[i] - m); sum += v[i]; }
    red[tid] = sum; __syncthreads();
    for (int s = 128; s > 0; s >>= 1) { if (tid < s) red[tid] += red[tid+s]; __syncthreads(); }
    float inv = 1.0f / red[0];
    #pragma unroll
    for (int i = 0; i < 2; i++) {
        int l = tid + i*256;
        if (l < LL) wv[l] = v[i] * inv;
    }
    __syncthreads();
    float acc = 0.f;
    const float* xb = g_x + (size_t)b*LL*DD;
    for (int l = 0; l < LL; l++) acc += wv[l] * xb[(size_t)l*DD + tid];
    out[b*DD + tid] = acc;
}

// ---------------- launcher ----------------
extern "C" void kernel_launch(void* const* d_in, const int* in_sizes, int n_in,
                              void* d_out, int out_size)
{
    const float* gene   = (const float*)d_in[0];
    const float* coords = (const float*)d_in[1];
    const float* w_in   = (const float*)d_in[2];
    const float* b_in   = (const float*)d_in[3];
    const float* w_cls  = (const float*)d_in[4];
    const float* b_cls  = (const float*)d_in[5];
    const float* qkv_w  = (const float*)d_in[6];
    const float* qkv_b  = (const float*)d_in[7];
    const float* ln1_g  = (const float*)d_in[8];
    const float* ln1_b  = (const float*)d_in[9];
    const float* ffn_w1 = (const float*)d_in[10];
    const float* ffn_b1 = (const float*)d_in[11];
    const float* ffn_w2 = (const float*)d_in[12];
    const float* ffn_b2 = (const float*)d_in[13];
    const float* ln2_g  = (const float*)d_in[14];
    const float* ln2_b  = (const float*)d_in[15];
    const float* th1_w  = (const float*)d_in[16];
    const float* th1_b  = (const float*)d_in[17];
    const float* bn_g   = (const float*)d_in[18];
    const float* bn_b   = (const float*)d_in[19];
    const float* th2_w  = (const float*)d_in[20];
    const float* th2_b  = (const float*)d_in[21];
    float* out = (float*)d_out;

    // one-time (per launch) weight split + transpose
    k_wsplit<<<dim3(768/32, 256/32, NLAYER), 256>>>(qkv_w,  256, 768,  OFF_QKV);
    k_wsplit<<<dim3(1024/32, 256/32, NLAYER), 256>>>(ffn_w1, 256, 1024, OFF_FF1);
    k_wsplit<<<dim3(256/32, 1024/32, NLAYER), 256>>>(ffn_w2, 1024, 256, OFF_FF2);

    k_input<<<BB*LL, 256>>>(gene, coords, w_in, b_in, w_cls, b_cls);

    for (int l = 0; l < NLAYER; l++) {
        size_t wbase = (size_t)l*WSTRIDE;
        k_gemm_mma<<<dim3(768/64, MMP/128), 256>>>(0, wbase + OFF_QKV,
                                                   qkv_b + (size_t)l*768, 768, 256);
        k_attn<<<dim3(8, BB*HH), 256>>>();
        k_addln<<<MM/8, 256>>>(ln1_g + (size_t)l*DD, ln1_b + (size_t)l*DD, 1);
        k_gemm_mma<<<dim3(1024/64, MMP/128), 256>>>(1, wbase + OFF_FF1,
                                                    ffn_b1 + (size_t)l*FFD, 1024, 256);
        k_gemm_mma<<<dim3(256/64, MMP/128), 256>>>(2, wbase + OFF_FF2,
                                                   ffn_b2 + (size_t)l*DD, 256, 1024);
        k_addln<<<MM/8, 256>>>(ln2_g + (size_t)l*DD, ln2_b + (size_t)l*DD, (l < 3) ? 1 : 0);
    }

    k_head<<<(MM + 7)/8, 256>>>(th1_w, th1_b, bn_g, bn_b, th2_w, th2_b);
    k_pool<<<BB, 256>>>(out);
}

// round 5
// speedup vs baseline: 2.6141x; 1.3502x over previous
#include <cuda_runtime.h>
#include <cuda_bf16.h>
#include <math.h>
#include <stdint.h>

#define BB 64
#define TOK 64
#define NTK 456
#define LL 457
#define DD 256
#define HH 8
#define HD 32
#define NLAYER 4
#define FFD 1024
#define MM (BB*LL)          // 29248
#define MMP 29312           // padded to multiple of 128

#define WSTRIDE 720896      // per-layer elems in split weight buffer
#define OFF_QKV 0
#define OFF_FF1 196608
#define OFF_FF2 458752

// ---------------- device scratch ----------------
__device__ float g_x   [(size_t)MMP*DD];
__device__ float g_tmp [(size_t)MMP*DD];
__device__ float g_hsc [MM];
// bf16 hi/lo planes
__device__ __nv_bfloat16 g_xh[(size_t)MMP*DD],   g_xl[(size_t)MMP*DD];
__device__ __nv_bfloat16 g_fh[(size_t)MMP*FFD],  g_fl[(size_t)MMP*FFD];
__device__ __nv_bfloat16 g_qvh[(size_t)MMP*768], g_qvl[(size_t)MMP*768];
__device__ __nv_bfloat16 g_wh[(size_t)NLAYER*WSTRIDE], g_wl[(size_t)NLAYER*WSTRIDE];

// ---------------- helpers ----------------
__device__ __forceinline__ void bsplit2(float a, float b,
                                        __nv_bfloat162& hi, __nv_bfloat162& lo)
{
    hi = __floats2bfloat162_rn(a, b);
    lo = __floats2bfloat162_rn(a - __bfloat162float(hi.x),
                               b - __bfloat162float(hi.y));
}

__device__ __forceinline__ void packsplit(float a, float b, uint32_t& h, uint32_t& l)
{
    __nv_bfloat162 hi, lo;
    bsplit2(a, b, hi, lo);
    h = *reinterpret_cast<uint32_t*>(&hi);
    l = *reinterpret_cast<uint32_t*>(&lo);
}

#define MMA16816(d, a0,a1,a2,a3, b0,b1) \
  asm volatile("mma.sync.aligned.m16n8k16.row.col.f32.bf16.bf16.f32 " \
    "{%0,%1,%2,%3}, {%4,%5,%6,%7}, {%8,%9}, {%0,%1,%2,%3};\n" \
    : "+f"(d[0]), "+f"(d[1]), "+f"(d[2]), "+f"(d[3]) \
    : "r"(a0), "r"(a1), "r"(a2), "r"(a3), "r"(b0), "r"(b1))

// ---------------- weight split + transpose: W[K][N] -> Wt planes [N][K] ----------------
__global__ __launch_bounds__(256) void k_wsplit(
    const float* __restrict__ W, int K, int N, size_t out_base)
{
    __shared__ float t[32][33];
    int l = blockIdx.z;
    const float* Wp = W + (size_t)l*K*N;
    int n0 = blockIdx.x*32, k0 = blockIdx.y*32;
    int tx = threadIdx.x & 31, ty = threadIdx.x >> 5;
    #pragma unroll
    for (int i = ty; i < 32; i += 8)
        t[i][tx] = Wp[(size_t)(k0+i)*N + n0 + tx];
    __syncthreads();
    #pragma unroll
    for (int i = ty; i < 32; i += 8) {
        float v = t[tx][i];   // = W[k0+tx][n0+i]
        size_t o = out_base + (size_t)l*WSTRIDE + (size_t)(n0+i)*K + (k0+tx);
        __nv_bfloat16 h = __float2bfloat16(v);
        g_wh[o] = h;
        g_wl[o] = __float2bfloat16(v - __bfloat162float(h));
    }
}

// ---------------- input projection + CLS (also emits bf16 planes) ----------------
__global__ __launch_bounds__(256) void k_input(
    const float* __restrict__ gene, const float* __restrict__ coords,
    const float* __restrict__ w_in, const float* __restrict__ b_in,
    const float* __restrict__ w_cls, const float* __restrict__ b_cls)
{
    int row = blockIdx.x;
    int b = row / LL, l = row % LL;
    int d = threadIdx.x;
    size_t off = (size_t)row*DD + d;
    float acc;
    if (l == 0) {
        acc = b_cls[d];
        #pragma unroll
        for (int k = 0; k < 3; k++) acc += coords[b*3 + k] * w_cls[k*DD + d];
    } else {
        __shared__ float sg[TOK];
        if (d < TOK) sg[d] = gene[(size_t)b*(NTK*TOK) + (size_t)(l-1)*TOK + d];
        __syncthreads();
        float a0 = b_in[d], a1 = 0.f;
        #pragma unroll 8
        for (int k = 0; k < TOK; k += 2) {
            a0 += sg[k]   * w_in[k*DD + d];
            a1 += sg[k+1] * w_in[(k+1)*DD + d];
        }
        acc = a0 + a1;
    }
    g_x[off] = acc;
    __nv_bfloat16 h = __float2bfloat16(acc);
    g_xh[off] = h;
    g_xl[off] = __float2bfloat16(acc - __bfloat162float(h));
}

// ---------------- bf16x3 tensor-core GEMM ----------------
// C[M,N] = A[M,K] @ W[K,N] + bias. Block tile 128x64, warp tile 32x32, KB=32.
// sel 0: A=x planes,   C -> qkv planes (N=768, K=256)
// sel 1: A=x planes,   C -> relu -> ffh planes (N=1024,K=256)
// sel 2: A=ffh planes, C=g_tmp fp32 (N=256, K=1024)
__global__ __launch_bounds__(256) void k_gemm_mma(
    int sel, size_t woff, const float* __restrict__ bias, int N, int K)
{
    __shared__ uint32_t AshH[128*20], AshL[128*20];   // [m][k-pair], pitch 20 words
    __shared__ uint32_t BshH[64*20],  BshL[64*20];    // [n][k-pair]

    const __nv_bfloat16 *Ah, *Al;
    if (sel == 2) { Ah = g_fh; Al = g_fl; }
    else          { Ah = g_xh; Al = g_xl; }

    int tid = threadIdx.x;
    int wid = tid >> 5, lane = tid & 31;
    int g = lane >> 2, c = lane & 3;
    int wm = wid & 3, wn = wid >> 2;
    int bm = blockIdx.y * 128, bn = blockIdx.x * 64;

    float acc[2][4][4] = {};

    for (int k0 = 0; k0 < K; k0 += 32) {
        #pragma unroll
        for (int e = 0; e < 2; e++) {
            int idx = tid + e*256;
            int m = idx >> 2, q = idx & 3;
            size_t go = (size_t)(bm+m)*K + k0 + q*8;
            *reinterpret_cast<uint4*>(AshH + m*20 + q*4) =
                *reinterpret_cast<const uint4*>(Ah + go);
            *reinterpret_cast<uint4*>(AshL + m*20 + q*4) =
                *reinterpret_cast<const uint4*>(Al + go);
        }
        {
            int n = tid >> 2, q = tid & 3;
            size_t go = woff + (size_t)(bn+n)*K + k0 + q*8;
            *reinterpret_cast<uint4*>(BshH + n*20 + q*4) =
                *reinterpret_cast<const uint4*>(g_wh + go);
            *reinterpret_cast<uint4*>(BshL + n*20 + q*4) =
                *reinterpret_cast<const uint4*>(g_wl + go);
        }
        __syncthreads();

        #pragma unroll
        for (int ks = 0; ks < 2; ks++) {
            uint32_t ah[2][4], al[2][4], bh[4][2], bl[4][2];
            #pragma unroll
            for (int mt = 0; mt < 2; mt++) {
                int m = wm*32 + mt*16 + g;
                int w0 = m*20 + ks*8 + c;
                int w1 = (m+8)*20 + ks*8 + c;
                ah[mt][0] = AshH[w0];   ah[mt][1] = AshH[w1];
                ah[mt][2] = AshH[w0+4]; ah[mt][3] = AshH[w1+4];
                al[mt][0] = AshL[w0];   al[mt][1] = AshL[w1];
                al[mt][2] = AshL[w0+4]; al[mt][3] = AshL[w1+4];
            }
            #pragma unroll
            for (int nt = 0; nt < 4; nt++) {
                int n = wn*32 + nt*8 + g;
                int w0 = n*20 + ks*8 + c;
                bh[nt][0] = BshH[w0]; bh[nt][1] = BshH[w0+4];
                bl[nt][0] = BshL[w0]; bl[nt][1] = BshL[w0+4];
            }
            #pragma unroll
            for (int mt = 0; mt < 2; mt++)
                #pragma unroll
                for (int nt = 0; nt < 4; nt++) {
                    MMA16816(acc[mt][nt], ah[mt][0],ah[mt][1],ah[mt][2],ah[mt][3],
                             bh[nt][0], bh[nt][1]);
                    MMA16816(acc[mt][nt], ah[mt][0],ah[mt][1],ah[mt][2],ah[mt][3],
                             bl[nt][0], bl[nt][1]);
                    MMA16816(acc[mt][nt], al[mt][0],al[mt][1],al[mt][2],al[mt][3],
                             bh[nt][0], bh[nt][1]);
                }
        }
        __syncthreads();
    }

    #pragma unroll
    for (int mt = 0; mt < 2; mt++) {
        int r0 = bm + wm*32 + mt*16 + g;
        #pragma unroll
        for (int nt = 0; nt < 4; nt++) {
            int cb = bn + wn*32 + nt*8 + 2*c;
            float2 bv = *reinterpret_cast<const float2*>(&bias[cb]);
            float v00 = acc[mt][nt][0] + bv.x, v01 = acc[mt][nt][1] + bv.y;
            float v10 = acc[mt][nt][2] + bv.x, v11 = acc[mt][nt][3] + bv.y;
            size_t o0 = (size_t)r0*N + cb;
            size_t o1 = (size_t)(r0+8)*N + cb;
            if (sel == 2) {
                *reinterpret_cast<float2*>(g_tmp + o0) = make_float2(v00, v01);
                *reinterpret_cast<float2*>(g_tmp + o1) = make_float2(v10, v11);
            } else {
                __nv_bfloat16 *H, *L;
                if (sel == 1) {
                    v00 = fmaxf(v00, 0.f); v01 = fmaxf(v01, 0.f);
                    v10 = fmaxf(v10, 0.f); v11 = fmaxf(v11, 0.f);
                    H = g_fh; L = g_fl;
                } else { H = g_qvh; L = g_qvl; }
                __nv_bfloat162 hi, lo;
                bsplit2(v00, v01, hi, lo);
                *reinterpret_cast<__nv_bfloat162*>(H + o0) = hi;
                *reinterpret_cast<__nv_bfloat162*>(L + o0) = lo;
                bsplit2(v10, v11, hi, lo);
                *reinterpret_cast<__nv_bfloat162*>(H + o1) = hi;
                *reinterpret_cast<__nv_bfloat162*>(L + o1) = lo;
            }
        }
    }
}

// ---------------- flash attention, bf16x3 tensor-core, register-resident P ----------------
// block = 128 q-rows x (b,h). 8 warps, each 16 q-rows. j chunk = 64.
__global__ __launch_bounds__(256) void k_attn()
{
    __shared__ uint32_t KsH[64*20], KsL[64*20];   // K [j][d-pair] pitch 20 words
    __shared__ uint32_t VtH[32*36], VtL[32*36];   // V^T [d][j-pair] pitch 36 words

    int gz = blockIdx.y;
    int b = gz >> 3, h = gz & 7;
    int qi0 = blockIdx.x * 128;
    int tid = threadIdx.x;
    int wq = tid >> 5, lane = tid & 31;
    int g = lane >> 2, c = lane & 3;

    const float slope = (h < 4) ? 1.0f : 0.5f;
    const float scale = 0.17677669529663689f;   // 1/sqrt(32)

    // Q fragments (rows qi0+wq*16+g / +8), hi & lo
    uint32_t qh[2][4], ql[2][4];
    {
        size_t r0 = ((size_t)b*LL + qi0 + wq*16 + g)*768 + h*HD;
        const __nv_bfloat16* ph = g_qvh + r0;
        const __nv_bfloat16* pl = g_qvl + r0;
        #pragma unroll
        for (int kt = 0; kt < 2; kt++) {
            qh[kt][0] = *(const uint32_t*)(ph + 16*kt + 2*c);
            qh[kt][1] = *(const uint32_t*)(ph + 8*768 + 16*kt + 2*c);
            qh[kt][2] = *(const uint32_t*)(ph + 16*kt + 2*c + 8);
            qh[kt][3] = *(const uint32_t*)(ph + 8*768 + 16*kt + 2*c + 8);
            ql[kt][0] = *(const uint32_t*)(pl + 16*kt + 2*c);
            ql[kt][1] = *(const uint32_t*)(pl + 8*768 + 16*kt + 2*c);
            ql[kt][2] = *(const uint32_t*)(pl + 16*kt + 2*c + 8);
            ql[kt][3] = *(const uint32_t*)(pl + 8*768 + 16*kt + 2*c + 8);
        }
    }

    float oacc[4][4] = {};
    float m_run[2] = {-1e30f, -1e30f};
    float s_run[2] = {0.f, 0.f};

    for (int j0 = 0; j0 < LL; j0 += 64) {
        __syncthreads();
        // load K tile + transposed V tile (hi & lo planes)
        {
            int j = tid >> 2, q = tid & 3;
            size_t krow = ((size_t)b*LL + j0 + j)*768 + 256 + h*HD;
            *reinterpret_cast<uint4*>(KsH + j*20 + q*4) =
                *reinterpret_cast<const uint4*>(g_qvh + krow + q*8);
            *reinterpret_cast<uint4*>(KsL + j*20 + q*4) =
                *reinterpret_cast<const uint4*>(g_qvl + krow + q*8);
            uint4 vh = *reinterpret_cast<const uint4*>(g_qvh + krow + 256 + q*8);
            uint4 vl = *reinterpret_cast<const uint4*>(g_qvl + krow + 256 + q*8);
            const __nv_bfloat16* eh = (const __nv_bfloat16*)&vh;
            const __nv_bfloat16* el = (const __nv_bfloat16*)&vl;
            #pragma unroll
            for (int i = 0; i < 8; i++) {
                ((__nv_bfloat16*)VtH)[(q*8+i)*72 + j] = eh[i];
                ((__nv_bfloat16*)VtL)[(q*8+i)*72 + j] = el[i];
            }
        }
        __syncthreads();

        // S = Q K^T (bf16x3)
        float sacc[8][4] = {};
        #pragma unroll
        for (int nt = 0; nt < 8; nt++) {
            int jrow = nt*8 + g;
            #pragma unroll
            for (int kt = 0; kt < 2; kt++) {
                uint32_t bh0 = KsH[jrow*20 + kt*8 + c];
                uint32_t bh1 = KsH[jrow*20 + kt*8 + c + 4];
                uint32_t bl0 = KsL[jrow*20 + kt*8 + c];
                uint32_t bl1 = KsL[jrow*20 + kt*8 + c + 4];
                MMA16816(sacc[nt], qh[kt][0],qh[kt][1],qh[kt][2],qh[kt][3], bh0, bh1);
                MMA16816(sacc[nt], qh[kt][0],qh[kt][1],qh[kt][2],qh[kt][3], bl0, bl1);
                MMA16816(sacc[nt], ql[kt][0],ql[kt][1],ql[kt][2],ql[kt][3], bh0, bh1);
            }
        }

        // online softmax on register fragments
        float corr[2];
        #pragma unroll
        for (int r = 0; r < 2; r++) {
            int qi = qi0 + wq*16 + g + r*8;
            float mloc = -1e30f;
            #pragma unroll
            for (int nt = 0; nt < 8; nt++) {
                #pragma unroll
                for (int e = 0; e < 2; e++) {
                    int kj = j0 + nt*8 + 2*c + e;
                    float v = sacc[nt][r*2+e]*scale - slope*fabsf((float)(qi - kj));
                    if (kj >= LL) v = -1e30f;
                    sacc[nt][r*2+e] = v;
                    mloc = fmaxf(mloc, v);
                }
            }
            mloc = fmaxf(mloc, __shfl_xor_sync(0xffffffffu, mloc, 1));
            mloc = fmaxf(mloc, __shfl_xor_sync(0xffffffffu, mloc, 2));
            float m_new = fmaxf(m_run[r], mloc);
            corr[r] = __expf(m_run[r] - m_new);
            float rs = 0.f;
            #pragma unroll
            for (int nt = 0; nt < 8; nt++) {
                #pragma unroll
                for (int e = 0; e < 2; e++) {
                    float p = __expf(sacc[nt][r*2+e] - m_new);
                    sacc[nt][r*2+e] = p;
                    rs += p;
                }
            }
            rs += __shfl_xor_sync(0xffffffffu, rs, 1);
            rs += __shfl_xor_sync(0xffffffffu, rs, 2);
            s_run[r] = s_run[r]*corr[r] + rs;
            m_run[r] = m_new;
        }
        #pragma unroll
        for (int nt = 0; nt < 4; nt++) {
            oacc[nt][0] *= corr[0]; oacc[nt][1] *= corr[0];
            oacc[nt][2] *= corr[1]; oacc[nt][3] *= corr[1];
        }

        // O += P V  (P packed from S accumulators, bf16x3)
        #pragma unroll
        for (int kt = 0; kt < 4; kt++) {
            uint32_t pah[4], pal[4];
            packsplit(sacc[2*kt][0],   sacc[2*kt][1],   pah[0], pal[0]);
            packsplit(sacc[2*kt][2],   sacc[2*kt][3],   pah[1], pal[1]);
            packsplit(sacc[2*kt+1][0], sacc[2*kt+1][1], pah[2], pal[2]);
            packsplit(sacc[2*kt+1][2], sacc[2*kt+1][3], pah[3], pal[3]);
            #pragma unroll
            for (int nt = 0; nt < 4; nt++) {
                int drow = nt*8 + g;
                uint32_t bh0 = VtH[drow*36 + kt*8 + c];
                uint32_t bh1 = VtH[drow*36 + kt*8 + c + 4];
                uint32_t bl0 = VtL[drow*36 + kt*8 + c];
                uint32_t bl1 = VtL[drow*36 + kt*8 + c + 4];
                MMA16816(oacc[nt], pah[0],pah[1],pah[2],pah[3], bh0, bh1);
                MMA16816(oacc[nt], pah[0],pah[1],pah[2],pah[3], bl0, bl1);
                MMA16816(oacc[nt], pal[0],pal[1],pal[2],pal[3], bh0, bh1);
            }
        }
    }

    // store O
    float inv0 = 1.0f / s_run[0];
    float inv1 = 1.0f / s_run[1];
    int qi = qi0 + wq*16 + g;
    if (qi < LL) {
        float* o = g_tmp + ((size_t)b*LL + qi)*DD + h*HD;
        #pragma unroll
        for (int nt = 0; nt < 4; nt++)
            *reinterpret_cast<float2*>(o + nt*8 + 2*c) =
                make_float2(oacc[nt][0]*inv0, oacc[nt][1]*inv0);
    }
    if (qi + 8 < LL) {
        float* o = g_tmp + ((size_t)b*LL + qi + 8)*DD + h*HD;
        #pragma unroll
        for (int nt = 0; nt < 4; nt++)
            *reinterpret_cast<float2*>(o + nt*8 + 2*c) =
                make_float2(oacc[nt][2]*inv1, oacc[nt][3]*inv1);
    }
}

// ---------------- x = LN(x + tmp), warp-per-row, optional bf16 plane emit ----------------
__global__ __launch_bounds__(256) void k_addln(
    const float* __restrict__ gamma, const float* __restrict__ beta, int planes)
{
    int w = threadIdx.x >> 5, lane = threadIdx.x & 31;
    int row = blockIdx.x*8 + w;
    size_t base = (size_t)row*DD + lane*4;

    float4 a0 = *reinterpret_cast<const float4*>(&g_x[base]);
    float4 a1 = *reinterpret_cast<const float4*>(&g_x[base+128]);
    float4 t0 = *reinterpret_cast<const float4*>(&g_tmp[base]);
    float4 t1 = *reinterpret_cast<const float4*>(&g_tmp[base+128]);
    float v[8] = {a0.x+t0.x, a0.y+t0.y, a0.z+t0.z, a0.w+t0.w,
                  a1.x+t1.x, a1.y+t1.y, a1.z+t1.z, a1.w+t1.w};
    float s = 0.f, s2 = 0.f;
    #pragma unroll
    for (int i = 0; i < 8; i++) { s += v[i]; s2 += v[i]*v[i]; }
    #pragma unroll
    for (int off = 16; off > 0; off >>= 1) {
        s  += __shfl_xor_sync(0xffffffffu, s,  off);
        s2 += __shfl_xor_sync(0xffffffffu, s2, off);
    }
    float mean = s * (1.0f/256.0f);
    float var  = s2 * (1.0f/256.0f) - mean*mean;
    float inv  = rsqrtf(var + 1e-5f);

    float4 gg0 = *reinterpret_cast<const float4*>(&gamma[lane*4]);
    float4 gg1 = *reinterpret_cast<const float4*>(&gamma[128 + lane*4]);
    float4 bb0 = *reinterpret_cast<const float4*>(&beta[lane*4]);
    float4 bb1 = *reinterpret_cast<const float4*>(&beta[128 + lane*4]);
    float gv[8] = {gg0.x,gg0.y,gg0.z,gg0.w, gg1.x,gg1.y,gg1.z,gg1.w};
    float bv[8] = {bb0.x,bb0.y,bb0.z,bb0.w, bb1.x,bb1.y,bb1.z,bb1.w};
    float y[8];
    #pragma unroll
    for (int i = 0; i < 8; i++) y[i] = (v[i]-mean)*inv*gv[i] + bv[i];

    *reinterpret_cast<float4*>(&g_x[base])     = make_float4(y[0],y[1],y[2],y[3]);
    *reinterpret_cast<float4*>(&g_x[base+128]) = make_float4(y[4],y[5],y[6],y[7]);
    if (planes) {
        #pragma unroll
        for (int p = 0; p < 4; p++) {
            size_t o = base + (p>>1)*128 + (p&1)*2;
            int i = p*2;
            __nv_bfloat162 hi, lo;
            bsplit2(y[i], y[i+1], hi, lo);
            *reinterpret_cast<__nv_bfloat162*>(g_xh + o) = hi;
            *reinterpret_cast<__nv_bfloat162*>(g_xl + o) = lo;
        }
    }
}

// ---------------- head ----------------
__global__ __launch_bounds__(256) void k_head(
    const float* __restrict__ th1_w, const float* __restrict__ th1_b,
    const float* __restrict__ bn_g,  const float* __restrict__ bn_b,
    const float* __restrict__ th2_w, const float* __restrict__ th2_b)
{
    __shared__ float sx[8][256];
    __shared__ float sw1[256*32];
    int tid = threadIdx.x;
    int w = tid >> 5, lane = tid & 31;
    int row0 = blockIdx.x * 8;
    #pragma unroll
    for (int e = 0; e < 32; e++) sw1[tid + e*256] = th1_w[tid + e*256];
    #pragma unroll
    for (int e = 0; e < 8; e++) {
        int idx = tid + e*256;
        int r = idx >> 8, c = idx & 255;
        int row = row0 + r;
        sx[r][c] = (row < MM) ? g_x[(size_t)row*DD + c] : 0.f;
    }
    __syncthreads();
    int row = row0 + w;
    if (row < MM) {
        float acc = th1_b[lane];
        #pragma unroll 8
        for (int k = 0; k < 256; k++) acc += sx[w][k] * sw1[k*32 + lane];
        acc = acc * (bn_g[lane] * rsqrtf(1.0f + 1e-5f)) + bn_b[lane];
        float t = tanhf(0.7978845608028654f * (acc + 0.044715f*acc*acc*acc));
        float ge = 0.5f * acc * (1.0f + t);
        float ps = ge * th2_w[lane];
        #pragma unroll
        for (int s = 16; s > 0; s >>= 1) ps += __shfl_xor_sync(0xffffffffu, ps, s);
        if (lane == 0) g_hsc[row] = ps + th2_b[0];
    }
}

// ---------------- softmax over L + pooled output ----------------
__global__ __launch_bounds__(256) void k_pool(float* __restrict__ out)
{
    int b = blockIdx.x, tid = threadIdx.x;
    __shared__ float wv[LL];
    __shared__ float red[256];
    float v[2];
    #pragma unroll
    for (int i = 0; i < 2; i++) {
        int l = tid + i*256;
        v[i] = (l < LL) ? g_hsc[b*LL + l] : -1e30f;
    }
    float m = fmaxf(v[0], v[1]);
    red[tid] = m; __syncthreads();
    for (int s = 128; s > 0; s >>= 1) { if (tid < s) red[tid] = fmaxf(red[tid], red[tid+s]); __syncthreads(); }
    m = red[0]; __syncthreads();
    float sum = 0.f;
    #pragma unroll
    for (int i = 0; i < 2; i++) { v[i] = __expf(v[i] - m); sum += v[i]; }
    red[tid] = sum; __syncthreads();
    for (int s = 128; s > 0; s >>= 1) { if (tid < s) red[tid] += red[tid+s]; __syncthreads(); }
    float inv = 1.0f / red[0];
    #pragma unroll
    for (int i = 0; i < 2; i++) {
        int l = tid + i*256;
        if (l < LL) wv[l] = v[i] * inv;
    }
    __syncthreads();
    float acc = 0.f;
    const float* xb = g_x + (size_t)b*LL*DD;
    for (int l = 0; l < LL; l++) acc += wv[l] * xb[(size_t)l*DD + tid];
    out[b*DD + tid] = acc;
}

// ---------------- launcher ----------------
extern "C" void kernel_launch(void* const* d_in, const int* in_sizes, int n_in,
                              void* d_out, int out_size)
{
    const float* gene   = (const float*)d_in[0];
    const float* coords = (const float*)d_in[1];
    const float* w_in   = (const float*)d_in[2];
    const float* b_in   = (const float*)d_in[3];
    const float* w_cls  = (const float*)d_in[4];
    const float* b_cls  = (const float*)d_in[5];
    const float* qkv_w  = (const float*)d_in[6];
    const float* qkv_b  = (const float*)d_in[7];
    const float* ln1_g  = (const float*)d_in[8];
    const float* ln1_b  = (const float*)d_in[9];
    const float* ffn_w1 = (const float*)d_in[10];
    const float* ffn_b1 = (const float*)d_in[11];
    const float* ffn_w2 = (const float*)d_in[12];
    const float* ffn_b2 = (const float*)d_in[13];
    const float* ln2_g  = (const float*)d_in[14];
    const float* ln2_b  = (const float*)d_in[15];
    const float* th1_w  = (const float*)d_in[16];
    const float* th1_b  = (const float*)d_in[17];
    const float* bn_g   = (const float*)d_in[18];
    const float* bn_b   = (const float*)d_in[19];
    const float* th2_w  = (const float*)d_in[20];
    const float* th2_b  = (const float*)d_in[21];
    float* out = (float*)d_out;

    k_wsplit<<<dim3(768/32, 256/32, NLAYER), 256>>>(qkv_w,  256, 768,  OFF_QKV);
    k_wsplit<<<dim3(1024/32, 256/32, NLAYER), 256>>>(ffn_w1, 256, 1024, OFF_FF1);
    k_wsplit<<<dim3(256/32, 1024/32, NLAYER), 256>>>(ffn_w2, 1024, 256, OFF_FF2);

    k_input<<<BB*LL, 256>>>(gene, coords, w_in, b_in, w_cls, b_cls);

    for (int l = 0; l < NLAYER; l++) {
        size_t wbase = (size_t)l*WSTRIDE;
        k_gemm_mma<<<dim3(768/64, MMP/128), 256>>>(0, wbase + OFF_QKV,
                                                   qkv_b + (size_t)l*768, 768, 256);
        k_attn<<<dim3(4, BB*HH), 256>>>();
        k_addln<<<MM/8, 256>>>(ln1_g + (size_t)l*DD, ln1_b + (size_t)l*DD, 1);
        k_gemm_mma<<<dim3(1024/64, MMP/128), 256>>>(1, wbase + OFF_FF1,
                                                    ffn_b1 + (size_t)l*FFD, 1024, 256);
        k_gemm_mma<<<dim3(256/64, MMP/128), 256>>>(2, wbase + OFF_FF2,
                                                   ffn_b2 + (size_t)l*DD, 256, 1024);
        k_addln<<<MM/8, 256>>>(ln2_g + (size_t)l*DD, ln2_b + (size_t)l*DD, (l < 3) ? 1 : 0);
    }

    k_head<<<(MM + 7)/8, 256>>>(th1_w, th1_b, bn_g, bn_b, th2_w, th2_b);
    k_pool<<<BB, 256>>>(out);
}